// round 12
// baseline (speedup 1.0000x reference)
#include <cuda_runtime.h>
#include <math.h>

#define N0   16
#define NN   96
#define ORIG 92
#define FDIM 64
#define KD   41
#define KDP  44          // padded nbr row (16B aligned float4 loads)
#define HD   128
#define NCONV 3
#define C2F  128         // 2*F
#define TOT  (N0*NN)     // 1536
#define EPSB 1e-5f

// ---------------- scratch (device globals; no allocation allowed) ----------
__device__ float g_fea[TOT*FDIM];            // current node features
__device__ float g_AB[TOT*2*C2F];            // [row][0:128]=A, [128:256]=B
__device__ float g_gated[(size_t)TOT*NN*C2F];// 75.5 MB pre-BN gate values
__device__ float g_summed[TOT*FDIM];
__device__ float g_sum1[C2F], g_sq1[C2F], g_mean1[C2F], g_istd1[C2F];
__device__ float g_sum2[FDIM], g_sq2[FDIM], g_mean2[FDIM], g_istd2[FDIM];
__device__ int   g_adj_mode;                 // 0=int32, 1=int64, 2=float32

__device__ __forceinline__ float softplusf(float x) {
    return (x > 20.f) ? x : log1pf(__expf(x));
}

// ---- classify adj dtype from its raw words (deterministic, data-driven) ----
// int64 0/1 values: every odd-index 32-bit word is the zero high-half.
// float 0/1 values: words are 0x00000000 or 0x3F800000.
// int32 0/1 values: words are 0 or 1, odd-index words ~50% nonzero.
__global__ void k_detect_adj(const unsigned int* __restrict__ a) {
    __shared__ int s_float, s_oddnz;
    if (threadIdx.x == 0) { s_float = 0; s_oddnz = 0; }
    __syncthreads();
    for (int i = threadIdx.x; i < 4096; i += blockDim.x) {
        unsigned int w = a[i];
        if (w == 0x3F800000u) atomicOr(&s_float, 1);
        if ((i & 1) && w != 0u) atomicOr(&s_oddnz, 1);
    }
    __syncthreads();
    if (threadIdx.x == 0)
        g_adj_mode = s_float ? 2 : (s_oddnz ? 0 : 1);
}

// fea = atom_fea @ emb_W + emb_b        (1536 x 92 @ 92 x 64)
__global__ void k_emb(const float* __restrict__ atom,
                      const float* __restrict__ W,
                      const float* __restrict__ b) {
    int row = blockIdx.x, t = threadIdx.x;     // 64 threads
    __shared__ float a_s[ORIG];
    for (int i = t; i < ORIG; i += FDIM) a_s[i] = atom[row*ORIG + i];
    __syncthreads();
    float acc = b[t];
#pragma unroll
    for (int k = 0; k < ORIG; k++) acc += a_s[k] * W[k*FDIM + t];
    g_fea[row*FDIM + t] = acc;
}

// AB = fea @ [W_f | W_a]   (1536 x 64 @ 64 x 256). Also zeroes BN1 stats.
__global__ void k_ab(const float* __restrict__ convW, int it) {
    int row = blockIdx.x, t = threadIdx.x;     // 256 threads
    __shared__ float f_s[FDIM];
    if (t < FDIM) f_s[t] = g_fea[row*FDIM + t];
    if (row == 0 && t < C2F) { g_sum1[t] = 0.f; g_sq1[t] = 0.f; }
    __syncthreads();
    const float* W = convW + (size_t)it*(2*FDIM+KD)*C2F;
    int c = t & (C2F-1);
    int half = t >> 7;                          // 0 -> W_f (rows 0:64), 1 -> W_a (rows 64:128)
    const float* Wp = W + (size_t)(half*FDIM)*C2F + c;
    float acc = 0.f;
#pragma unroll
    for (int k = 0; k < FDIM; k++) acc += f_s[k] * Wp[(size_t)k*C2F];
    g_AB[row*(2*C2F) + half*C2F + c] = acc;
}

// gated[b,i,j,c] = A + adj*B + nbr@W_n + bias ; accumulate BN1 sum/sumsq.
// One block per (b,i) node. Thread = output channel c. W_n column in registers.
__global__ void __launch_bounds__(C2F)
k_gated(const float* __restrict__ nbr, const void* __restrict__ adjp,
        const float* __restrict__ convW, const float* __restrict__ convB, int it) {
    int row = blockIdx.x, t = threadIdx.x;     // 128 threads
    __shared__ float Wn_s[KD*C2F];             // 20.99 KB
    __shared__ __align__(16) float nbr_s[NN*KDP]; // 16.9 KB, rows padded to 44
    __shared__ float adj_s[NN];
    __shared__ float A_s[C2F], B_s[C2F];

    const float* W = convW + (size_t)it*(2*FDIM+KD)*C2F + (size_t)(2*FDIM)*C2F;
    for (int i = t; i < KD*C2F; i += C2F) Wn_s[i] = W[i];
    const float* nrow = nbr + (size_t)row*NN*KD;
    for (int i = t; i < NN*KD; i += C2F) {
        int j = i / KD, k = i - j*KD;
        nbr_s[j*KDP + k] = nrow[i];
    }
    if (t < NN) {
        size_t idx = (size_t)row*NN + t;
        int mode = g_adj_mode;
        float av;
        if (mode == 2)      av = ((const float*)adjp)[idx];
        else if (mode == 1) av = (float)(((const long long*)adjp)[idx]);
        else                av = (float)(((const int*)adjp)[idx]);
        adj_s[t] = av;
    }
    A_s[t] = g_AB[row*(2*C2F) + t];
    B_s[t] = g_AB[row*(2*C2F) + C2F + t];
    __syncthreads();

    float wn[KD];
#pragma unroll
    for (int k = 0; k < KD; k++) wn[k] = Wn_s[k*C2F + t];

    float a0 = A_s[t] + convB[it*C2F + t];
    float b0 = B_s[t];
    float s = 0.f, s2 = 0.f;
    float* gout = g_gated + (size_t)row*NN*C2F + t;

    for (int j = 0; j < NN; j++) {
        float acc = a0 + adj_s[j] * b0;
        const float4* nr4 = reinterpret_cast<const float4*>(nbr_s + j*KDP);
#pragma unroll
        for (int q = 0; q < 10; q++) {
            float4 v = nr4[q];
            acc += v.x*wn[4*q+0] + v.y*wn[4*q+1] + v.z*wn[4*q+2] + v.w*wn[4*q+3];
        }
        acc += nbr_s[j*KDP + 40] * wn[40];
        gout[(size_t)j*C2F] = acc;
        s += acc; s2 += acc*acc;
    }
    atomicAdd(&g_sum1[t], s);
    atomicAdd(&g_sq1[t], s2);
}

// finalize BN1 stats; zero BN2 accumulators
__global__ void k_stats1() {
    int t = threadIdx.x;                       // 128 threads
    const float inv_n = 1.f / (float)(TOT*NN);
    float m = g_sum1[t] * inv_n;
    float v = g_sq1[t] * inv_n - m*m;
    g_mean1[t] = m;
    g_istd1[t] = rsqrtf(v + EPSB);
    if (t < FDIM) { g_sum2[t] = 0.f; g_sq2[t] = 0.f; }
}

// summed[b,i,f] = sum_j sigmoid(bn1(filt)) * softplus(bn1(core)); BN2 stats.
__global__ void k_summed(const float* __restrict__ bn1g,
                         const float* __restrict__ bn1b, int it) {
    int row = blockIdx.x, t = threadIdx.x;     // 64 threads
    float mf = g_mean1[t],        isf = g_istd1[t];
    float mc = g_mean1[FDIM + t], isc = g_istd1[FDIM + t];
    float gf = bn1g[it*C2F + t],        bf = bn1b[it*C2F + t];
    float gc = bn1g[it*C2F + FDIM + t], bc = bn1b[it*C2F + FDIM + t];
    const float* gin = g_gated + (size_t)row*NN*C2F;
    float acc = 0.f;
    for (int j = 0; j < NN; j++) {
        float xf = (gin[(size_t)j*C2F + t]        - mf) * isf * gf + bf;
        float xc = (gin[(size_t)j*C2F + FDIM + t] - mc) * isc * gc + bc;
        float sig = 1.f / (1.f + __expf(-xf));
        acc += sig * softplusf(xc);
    }
    g_summed[row*FDIM + t] = acc;
    atomicAdd(&g_sum2[t], acc);
    atomicAdd(&g_sq2[t], acc*acc);
}

__global__ void k_stats2() {
    int t = threadIdx.x;                       // 64 threads
    const float inv_n = 1.f / (float)TOT;
    float m = g_sum2[t] * inv_n;
    float v = g_sq2[t] * inv_n - m*m;
    g_mean2[t] = m;
    g_istd2[t] = rsqrtf(v + EPSB);
}

// fea = softplus(fea + bn2(summed))
__global__ void k_update(const float* __restrict__ bn2g,
                         const float* __restrict__ bn2b, int it) {
    int idx = blockIdx.x*256 + threadIdx.x;
    int f = idx & (FDIM-1);
    float y = (g_summed[idx] - g_mean2[f]) * g_istd2[f] * bn2g[it*FDIM + f] + bn2b[it*FDIM + f];
    g_fea[idx] = softplusf(g_fea[idx] + y);
}

// head: crys = mean_n fea; out = softplus(softplus(crys)@fcW + fcb)@outW + outb
__global__ void k_head(const float* __restrict__ fcW, const float* __restrict__ fcb,
                       const float* __restrict__ outW, const float* __restrict__ outb,
                       float* __restrict__ out) {
    int b = blockIdx.x, t = threadIdx.x;       // 128 threads
    __shared__ float crys[FDIM];
    __shared__ float red[HD];
    if (t < FDIM) {
        float acc = 0.f;
        for (int n = 0; n < NN; n++) acc += g_fea[(b*NN + n)*FDIM + t];
        crys[t] = softplusf(acc * (1.f/(float)NN));
    }
    __syncthreads();
    float h = fcb[t];
#pragma unroll
    for (int f = 0; f < FDIM; f++) h += crys[f] * fcW[f*HD + t];
    h = softplusf(h);
    red[t] = h * outW[t];
    __syncthreads();
    for (int s = HD/2; s > 0; s >>= 1) {
        if (t < s) red[t] += red[t + s];
        __syncthreads();
    }
    if (t == 0) out[b] = red[0] + outb[0];
}

extern "C" void kernel_launch(void* const* d_in, const int* in_sizes, int n_in,
                              void* d_out, int out_size) {
    const float*      atom  = (const float*)d_in[0];
    const float*      nbr   = (const float*)d_in[1];
    const void*       adj   = d_in[2];          // dtype auto-detected on device
    const float*      embW  = (const float*)d_in[3];
    const float*      embB  = (const float*)d_in[4];
    const float*      convW = (const float*)d_in[5];
    const float*      convB = (const float*)d_in[6];
    const float*      bn1g  = (const float*)d_in[7];
    const float*      bn1b  = (const float*)d_in[8];
    const float*      bn2g  = (const float*)d_in[9];
    const float*      bn2b  = (const float*)d_in[10];
    const float*      fcW   = (const float*)d_in[11];
    const float*      fcb   = (const float*)d_in[12];
    const float*      outW  = (const float*)d_in[13];
    const float*      outb  = (const float*)d_in[14];
    float* out = (float*)d_out;

    k_detect_adj<<<1, 256>>>((const unsigned int*)adj);
    k_emb<<<TOT, FDIM>>>(atom, embW, embB);
    for (int it = 0; it < NCONV; it++) {
        k_ab<<<TOT, 2*C2F>>>(convW, it);
        k_gated<<<TOT, C2F>>>(nbr, adj, convW, convB, it);
        k_stats1<<<1, C2F>>>();
        k_summed<<<TOT, FDIM>>>(bn1g, bn1b, it);
        k_stats2<<<1, FDIM>>>();
        k_update<<<(TOT*FDIM)/256, 256>>>(bn2g, bn2b, it);
    }
    k_head<<<N0, HD>>>(fcW, fcb, outW, outb, out);
}

// round 13
// speedup vs baseline: 1.4006x; 1.4006x over previous
#include <cuda_runtime.h>
#include <math.h>

#define N0   16
#define NN   96
#define ORIG 92
#define FDIM 64
#define KD   41
#define KDP  44          // padded nbr row (16B aligned float4 loads)
#define HD   128
#define NCONV 3
#define C2F  128         // 2*F
#define TOT  (N0*NN)     // 1536
#define EPSB 1e-5f
#define ABROWS 8

// ---------------- scratch (device globals; no allocation allowed) ----------
__device__ float g_fea[TOT*FDIM];            // current node features
__device__ float g_AB[TOT*2*C2F];            // [row][0:128]=A, [128:256]=B
__device__ float g_gated[(size_t)TOT*NN*C2F];// 75.5 MB pre-BN gate values
__device__ float g_summed[TOT*FDIM];
__device__ float g_sum1[C2F], g_sq1[C2F], g_mean1[C2F], g_istd1[C2F];
__device__ float g_sum2[FDIM], g_sq2[FDIM], g_mean2[FDIM], g_istd2[FDIM];
__device__ int   g_adj_mode;                 // 0=int32, 1=int64, 2=float32

// stable fast softplus: max(x,0) + log(1+exp(-|x|));  __logf arg in (1,2] so
// relative error ~1e-7 absolute in the log term. MUFU-only, no branches.
__device__ __forceinline__ float softplusf(float x) {
    return fmaxf(x, 0.f) + __logf(1.f + __expf(-fabsf(x)));
}
__device__ __forceinline__ float sigmoidf(float x) {
    return __fdividef(1.f, 1.f + __expf(-x));
}

// ---- classify adj dtype from its raw words (deterministic, data-driven) ----
__global__ void k_detect_adj(const unsigned int* __restrict__ a) {
    __shared__ int s_float, s_oddnz;
    if (threadIdx.x == 0) { s_float = 0; s_oddnz = 0; }
    __syncthreads();
    for (int i = threadIdx.x; i < 4096; i += blockDim.x) {
        unsigned int w = a[i];
        if (w == 0x3F800000u) atomicOr(&s_float, 1);
        if ((i & 1) && w != 0u) atomicOr(&s_oddnz, 1);
    }
    __syncthreads();
    if (threadIdx.x == 0)
        g_adj_mode = s_float ? 2 : (s_oddnz ? 0 : 1);
}

// fea = atom_fea @ emb_W + emb_b        (1536 x 92 @ 92 x 64)
__global__ void k_emb(const float* __restrict__ atom,
                      const float* __restrict__ W,
                      const float* __restrict__ b) {
    int row = blockIdx.x, t = threadIdx.x;     // 64 threads
    __shared__ float a_s[ORIG];
    for (int i = t; i < ORIG; i += FDIM) a_s[i] = atom[row*ORIG + i];
    __syncthreads();
    float acc = b[t];
#pragma unroll
    for (int k = 0; k < ORIG; k++) acc += a_s[k] * W[k*FDIM + t];
    g_fea[row*FDIM + t] = acc;
}

// AB = fea @ [W_f | W_a]   (1536 x 64 @ 64 x 256), 8 rows per block so the
// weight panel is read from L2 once per 8 rows. Also zeroes BN1 stats.
__global__ void __launch_bounds__(256)
k_ab(const float* __restrict__ convW, int it) {
    int r0 = blockIdx.x * ABROWS, t = threadIdx.x;   // 256 threads
    __shared__ float f_s[ABROWS][FDIM];
    for (int i = t; i < ABROWS*FDIM; i += 256)
        f_s[i >> 6][i & 63] = g_fea[r0*FDIM + i];
    if (blockIdx.x == 0 && t < C2F) { g_sum1[t] = 0.f; g_sq1[t] = 0.f; }
    __syncthreads();
    const float* W = convW + (size_t)it*(2*FDIM+KD)*C2F;
    int c = t & (C2F-1);
    int half = t >> 7;                          // 0 -> W_f, 1 -> W_a
    const float* Wp = W + (size_t)(half*FDIM)*C2F + c;
    float acc[ABROWS];
#pragma unroll
    for (int r = 0; r < ABROWS; r++) acc[r] = 0.f;
#pragma unroll 8
    for (int k = 0; k < FDIM; k++) {
        float w = Wp[(size_t)k*C2F];
#pragma unroll
        for (int r = 0; r < ABROWS; r++) acc[r] += f_s[r][k] * w;
    }
#pragma unroll
    for (int r = 0; r < ABROWS; r++)
        g_AB[(r0+r)*(2*C2F) + half*C2F + c] = acc[r];
}

// gated[b,i,j,c] = A + adj*B + nbr@W_n + bias ; accumulate BN1 sum/sumsq.
// ILP: 4 partial accumulators per j, j unrolled x2 -> 8 independent FFMA chains.
__global__ void __launch_bounds__(C2F)
k_gated(const float* __restrict__ nbr, const void* __restrict__ adjp,
        const float* __restrict__ convW, const float* __restrict__ convB, int it) {
    int row = blockIdx.x, t = threadIdx.x;     // 128 threads
    __shared__ float Wn_s[KD*C2F];             // 20.99 KB
    __shared__ __align__(16) float nbr_s[NN*KDP]; // 16.9 KB
    __shared__ float adj_s[NN];
    __shared__ float A_s[C2F], B_s[C2F];

    const float* W = convW + (size_t)it*(2*FDIM+KD)*C2F + (size_t)(2*FDIM)*C2F;
    for (int i = t; i < KD*C2F; i += C2F) Wn_s[i] = W[i];
    const float* nrow = nbr + (size_t)row*NN*KD;
    for (int i = t; i < NN*KD; i += C2F) {
        int j = i / KD, k = i - j*KD;
        nbr_s[j*KDP + k] = nrow[i];
    }
    if (t < NN) {
        size_t idx = (size_t)row*NN + t;
        int mode = g_adj_mode;
        float av;
        if (mode == 2)      av = ((const float*)adjp)[idx];
        else if (mode == 1) av = (float)(((const long long*)adjp)[idx]);
        else                av = (float)(((const int*)adjp)[idx]);
        adj_s[t] = av;
    }
    A_s[t] = g_AB[row*(2*C2F) + t];
    B_s[t] = g_AB[row*(2*C2F) + C2F + t];
    __syncthreads();

    float wn[KD];
#pragma unroll
    for (int k = 0; k < KD; k++) wn[k] = Wn_s[k*C2F + t];

    float a0 = A_s[t] + convB[it*C2F + t];
    float b0 = B_s[t];
    float s = 0.f, s2 = 0.f;
    float* gout = g_gated + (size_t)row*NN*C2F + t;

#pragma unroll 2
    for (int jj = 0; jj < NN; jj += 2) {
#pragma unroll
        for (int u = 0; u < 2; u++) {
            int j = jj + u;
            const float4* nr4 = reinterpret_cast<const float4*>(nbr_s + j*KDP);
            float p0 = 0.f, p1 = 0.f, p2 = 0.f, p3 = 0.f;
#pragma unroll
            for (int q = 0; q < 10; q++) {
                float4 v = nr4[q];
                p0 += v.x * wn[4*q+0];
                p1 += v.y * wn[4*q+1];
                p2 += v.z * wn[4*q+2];
                p3 += v.w * wn[4*q+3];
            }
            p0 += nbr_s[j*KDP + 40] * wn[40];
            float acc = (a0 + adj_s[j]*b0) + ((p0 + p1) + (p2 + p3));
            gout[(size_t)j*C2F] = acc;
            s += acc; s2 += acc*acc;
        }
    }
    atomicAdd(&g_sum1[t], s);
    atomicAdd(&g_sq1[t], s2);
}

// finalize BN1 stats; zero BN2 accumulators
__global__ void k_stats1() {
    int t = threadIdx.x;                       // 128 threads
    const float inv_n = 1.f / (float)(TOT*NN);
    float m = g_sum1[t] * inv_n;
    float v = g_sq1[t] * inv_n - m*m;
    g_mean1[t] = m;
    g_istd1[t] = rsqrtf(v + EPSB);
    if (t < FDIM) { g_sum2[t] = 0.f; g_sq2[t] = 0.f; }
}

// summed[b,i,f] = sum_j sigmoid(bn1(filt)) * softplus(bn1(core)); BN2 stats.
// 128 threads: two j-phases in parallel, combined through shared memory.
__global__ void __launch_bounds__(C2F)
k_summed(const float* __restrict__ bn1g, const float* __restrict__ bn1b, int it) {
    int row = blockIdx.x, t = threadIdx.x;     // 128 threads
    int c = t & 63, half = t >> 6;
    float mf = g_mean1[c],        isf = g_istd1[c];
    float mc = g_mean1[FDIM + c], isc = g_istd1[FDIM + c];
    float gf = bn1g[it*C2F + c],        bf = bn1b[it*C2F + c];
    float gc = bn1g[it*C2F + FDIM + c], bc = bn1b[it*C2F + FDIM + c];
    // fold BN affine: y = x*K + B
    float kf = isf*gf, Bf = bf - mf*kf;
    float kc = isc*gc, Bc = bc - mc*kc;
    const float* gin = g_gated + (size_t)row*NN*C2F;
    float acc = 0.f;
    for (int j = half; j < NN; j += 2) {
        float xf = gin[(size_t)j*C2F + c]        * kf + Bf;
        float xc = gin[(size_t)j*C2F + FDIM + c] * kc + Bc;
        acc += sigmoidf(xf) * softplusf(xc);
    }
    __shared__ float part[C2F];
    part[t] = acc;
    __syncthreads();
    if (half == 0) {
        float tot = part[c] + part[c + 64];
        g_summed[row*FDIM + c] = tot;
        atomicAdd(&g_sum2[c], tot);
        atomicAdd(&g_sq2[c], tot*tot);
    }
}

__global__ void k_stats2() {
    int t = threadIdx.x;                       // 64 threads
    const float inv_n = 1.f / (float)TOT;
    float m = g_sum2[t] * inv_n;
    float v = g_sq2[t] * inv_n - m*m;
    g_mean2[t] = m;
    g_istd2[t] = rsqrtf(v + EPSB);
}

// fea = softplus(fea + bn2(summed))
__global__ void k_update(const float* __restrict__ bn2g,
                         const float* __restrict__ bn2b, int it) {
    int idx = blockIdx.x*256 + threadIdx.x;
    int f = idx & (FDIM-1);
    float y = (g_summed[idx] - g_mean2[f]) * g_istd2[f] * bn2g[it*FDIM + f] + bn2b[it*FDIM + f];
    g_fea[idx] = softplusf(g_fea[idx] + y);
}

// head: crys = mean_n fea; out = softplus(softplus(crys)@fcW + fcb)@outW + outb
__global__ void k_head(const float* __restrict__ fcW, const float* __restrict__ fcb,
                       const float* __restrict__ outW, const float* __restrict__ outb,
                       float* __restrict__ out) {
    int b = blockIdx.x, t = threadIdx.x;       // 128 threads
    __shared__ float crys[FDIM];
    __shared__ float red[HD];
    if (t < FDIM) {
        float acc = 0.f;
        for (int n = 0; n < NN; n++) acc += g_fea[(b*NN + n)*FDIM + t];
        crys[t] = softplusf(acc * (1.f/(float)NN));
    }
    __syncthreads();
    float h = fcb[t];
#pragma unroll
    for (int f = 0; f < FDIM; f++) h += crys[f] * fcW[f*HD + t];
    h = softplusf(h);
    red[t] = h * outW[t];
    __syncthreads();
    for (int s = HD/2; s > 0; s >>= 1) {
        if (t < s) red[t] += red[t + s];
        __syncthreads();
    }
    if (t == 0) out[b] = red[0] + outb[0];
}

extern "C" void kernel_launch(void* const* d_in, const int* in_sizes, int n_in,
                              void* d_out, int out_size) {
    const float*      atom  = (const float*)d_in[0];
    const float*      nbr   = (const float*)d_in[1];
    const void*       adj   = d_in[2];          // dtype auto-detected on device
    const float*      embW  = (const float*)d_in[3];
    const float*      embB  = (const float*)d_in[4];
    const float*      convW = (const float*)d_in[5];
    const float*      convB = (const float*)d_in[6];
    const float*      bn1g  = (const float*)d_in[7];
    const float*      bn1b  = (const float*)d_in[8];
    const float*      bn2g  = (const float*)d_in[9];
    const float*      bn2b  = (const float*)d_in[10];
    const float*      fcW   = (const float*)d_in[11];
    const float*      fcb   = (const float*)d_in[12];
    const float*      outW  = (const float*)d_in[13];
    const float*      outb  = (const float*)d_in[14];
    float* out = (float*)d_out;

    k_detect_adj<<<1, 256>>>((const unsigned int*)adj);
    k_emb<<<TOT, FDIM>>>(atom, embW, embB);
    for (int it = 0; it < NCONV; it++) {
        k_ab<<<TOT/ABROWS, 256>>>(convW, it);
        k_gated<<<TOT, C2F>>>(nbr, adj, convW, convB, it);
        k_stats1<<<1, C2F>>>();
        k_summed<<<TOT, C2F>>>(bn1g, bn1b, it);
        k_stats2<<<1, FDIM>>>();
        k_update<<<(TOT*FDIM)/256, 256>>>(bn2g, bn2b, it);
    }
    k_head<<<N0, HD>>>(fcW, fcb, outW, outb, out);
}